// round 6
// baseline (speedup 1.0000x reference)
#include <cuda_runtime.h>
#include <cstdint>

#define B_TOTAL 131072
#define NDIM 64
#define RANK 32
#define NPAIR (NDIM * NDIM)
#define MID_STRIDE (RANK*NDIM*RANK)
#define ROW_STRIDE (NDIM*RANK)

typedef unsigned long long ull;

__device__ float g_vbuf[B_TOTAL * RANK];
__device__ float g_A[NPAIR * RANK];
__device__ float g_Z[NPAIR * RANK];
__device__ float g_P1[NPAIR * RANK * RANK];
__device__ float g_P2[NPAIR * RANK * RANK];
__device__ int   g_perm[2][B_TOTAL];
__device__ int   g_hist[2][NPAIR];
__device__ int   g_base[2][NPAIR + 1];
__device__ int   g_cur[2][NPAIR];

__device__ __forceinline__ int sniff64(const int32_t* raw) {
    unsigned int h = 0;
#pragma unroll
    for (int i = 0; i < 16; i++) h |= (unsigned int)raw[2 * i + 1];
    return (h == 0u) ? 1 : 0;
}
__device__ __forceinline__ int get_idx(const int32_t* raw, int e, int k, int is64) {
    int t;
    if (is64) t = (int)((const long long*)raw)[(long long)e * 8 + k];
    else      t = raw[e * 8 + k];
    return min(max(t, 0), NDIM - 1);
}
__device__ __forceinline__ ull pack2(float x, float y) {
    ull r; asm("mov.b64 %0,{%1,%2};" : "=l"(r) : "f"(x), "f"(y)); return r;
}
__device__ __forceinline__ void unpack2(ull v, float& x, float& y) {
    asm("mov.b64 {%0,%1},%2;" : "=f"(x), "=f"(y) : "l"(v));
}
__device__ __forceinline__ void fma2(ull& d, ull a, ull b) {
    asm("fma.rn.f32x2 %0,%1,%2,%0;" : "+l"(d) : "l"(a), "l"(b));
}

__global__ __launch_bounds__(256)
void k1_prep(const int32_t* __restrict__ raw,
             const float* __restrict__ core0,
             const float* __restrict__ mids,
             const float* __restrict__ cl) {
    __shared__ float S[RANK * 34];
    const int b = blockIdx.x, tid = threadIdx.x;
    const int warp = tid >> 5, lane = tid & 31;

    if (b < 64) {
        const int is64 = sniff64(raw);
#pragma unroll
        for (int i = 0; i < 8; i++) {
            const int e = b * 2048 + i * 256 + tid;
            int k0 = get_idx(raw, e, 2, is64) * NDIM + get_idx(raw, e, 3, is64);
            int k1 = get_idx(raw, e, 4, is64) * NDIM + get_idx(raw, e, 5, is64);
            atomicAdd(&g_hist[0][k0], 1);
            atomicAdd(&g_hist[1][k1], 1);
        }
    } else if (b < 128) {
        const int j0 = b - 64;
        if (tid < RANK) S[tid] = core0[j0 * RANK + tid];
        __syncthreads();
#pragma unroll
        for (int t = 0; t < 8; t++) {
            const int j1 = warp * 8 + t;
            float acc = 0.0f;
#pragma unroll
            for (int r = 0; r < RANK; r++)
                acc = fmaf(S[r], mids[r * ROW_STRIDE + j1 * RANK + lane], acc);
            g_A[(j0 * NDIM + j1) * RANK + lane] = acc;
        }
    } else if (b < 192) {
        const int j6 = b - 128;
        const float* M5 = mids + 5 * MID_STRIDE;
        for (int i = tid; i < RANK * RANK; i += 256) {
            int r = i >> 5, s = i & 31;
            S[s * 34 + r] = M5[r * ROW_STRIDE + j6 * RANK + s];
        }
        __syncthreads();
#pragma unroll
        for (int t = 0; t < 8; t++) {
            const int j7 = warp * 8 + t;
            float acc = 0.0f;
#pragma unroll
            for (int s = 0; s < RANK; s++)
                acc = fmaf(cl[s * NDIM + j7], S[s * 34 + lane], acc);
            g_Z[(j6 * NDIM + j7) * RANK + lane] = acc;
        }
    } else {
        const int which = (b < 704) ? 0 : 1;
        const int x = b - (which ? 704 : 192);
        const int ja = x >> 3;
        const float* Ma = mids + (which ? 3 : 1) * MID_STRIDE;
        const float* Mb = mids + (which ? 4 : 2) * MID_STRIDE;
        float* P = which ? g_P2 : g_P1;

        for (int i = tid; i < RANK * RANK; i += 256) {
            int r = i >> 5, m = i & 31;
            S[m * 34 + r] = Ma[r * ROW_STRIDE + ja * RANK + m];
        }
        __syncthreads();

        const int jb = (x & 7) * 8 + warp;
        float m2[RANK];
#pragma unroll
        for (int m = 0; m < RANK; m++)
            m2[m] = Mb[m * ROW_STRIDE + jb * RANK + lane];

        ull acc2[16];
#pragma unroll
        for (int q = 0; q < 16; q++) acc2[q] = 0ull;
#pragma unroll
        for (int m = 0; m < RANK; m++) {
            const ull dup = pack2(m2[m], m2[m]);
            const ull* Sp = reinterpret_cast<const ull*>(S + m * 34);
#pragma unroll
            for (int rp = 0; rp < 16; rp++) fma2(acc2[rp], Sp[rp], dup);
        }
        float* Pp = P + (ja * NDIM + jb) * (RANK * RANK);
#pragma unroll
        for (int rp = 0; rp < 16; rp++) {
            float a, c;
            unpack2(acc2[rp], a, c);
            Pp[(2 * rp) * RANK + lane]     = a;
            Pp[(2 * rp + 1) * RANK + lane] = c;
        }
    }
}

__global__ __launch_bounds__(1024)
void k2_scan() {
    __shared__ int sh[1024];
    const int m = blockIdx.x, t = threadIdx.x;
    int4 v4 = reinterpret_cast<const int4*>(g_hist[m])[t];
    int vals[4] = {v4.x, v4.y, v4.z, v4.w};
    int s = vals[0] + vals[1] + vals[2] + vals[3];
    sh[t] = s;
    __syncthreads();
    for (int off = 1; off < 1024; off <<= 1) {
        int u = (t >= off) ? sh[t - off] : 0;
        __syncthreads();
        sh[t] += u;
        __syncthreads();
    }
    int run = sh[t] - s;
#pragma unroll
    for (int i = 0; i < 4; i++) {
        int bin = t * 4 + i;
        g_base[m][bin] = run;
        g_cur[m][bin]  = run;
        g_hist[m][bin] = 0;
        run += vals[i];
    }
    if (t == 1023) g_base[m][NPAIR] = B_TOTAL;
}

__global__ __launch_bounds__(256)
void k3_scatter(const int32_t* __restrict__ raw) {
    const int is64 = sniff64(raw);
    for (int e = blockIdx.x * 256 + threadIdx.x; e < B_TOTAL; e += gridDim.x * 256) {
        int k0 = get_idx(raw, e, 2, is64) * NDIM + get_idx(raw, e, 3, is64);
        int k1 = get_idx(raw, e, 4, is64) * NDIM + get_idx(raw, e, 5, is64);
        g_perm[0][atomicAdd(&g_cur[0][k0], 1)] = e;
        g_perm[1][atomicAdd(&g_cur[1][k1], 1)] = e;
    }
}

// 8 warps/block, warp-per-bin, no smem; lane owns one element.
// acc[i] <-> slice-row ull index i <-> output floats {2i, 2i+1}.
template <bool FIRST, bool LAST>
__global__ __launch_bounds__(256, 3)
void step_kernel(int S, const int32_t* __restrict__ raw,
                 const float* __restrict__ Ptab, float* __restrict__ out) {
    const int lane = threadIdx.x & 31;
    const int bin = blockIdx.x * 8 + (threadIdx.x >> 5);
    const int lo = g_base[S][bin], hi = g_base[S][bin + 1];
    if (lo >= hi) return;

    const ulonglong2* __restrict__ sl =
        reinterpret_cast<const ulonglong2*>(Ptab + bin * (RANK * RANK));
    const int is64 = (FIRST || LAST) ? sniff64(raw) : 0;

    for (int base = lo; base < hi; base += 32) {
        const bool act = (base + lane < hi);
        const int e = g_perm[S][act ? base + lane : base];

        const float4* __restrict__ v4;
        if (FIRST) {
            int rowidx = get_idx(raw, e, 0, is64) * NDIM + get_idx(raw, e, 1, is64);
            v4 = reinterpret_cast<const float4*>(g_A + rowidx * RANK);
        } else {
            v4 = reinterpret_cast<const float4*>(g_vbuf + e * RANK);
        }

        ull acc[16];
#pragma unroll
        for (int q = 0; q < 16; q++) acc[q] = 0ull;

#pragma unroll
        for (int g = 0; g < 8; g++) {
            const float4 v = v4[g];
            const float vs[4] = {v.x, v.y, v.z, v.w};
#pragma unroll
            for (int t = 0; t < 4; t++) {
                const int r = g * 4 + t;
                const ull dup = pack2(vs[t], vs[t]);
                const ulonglong2* __restrict__ row = sl + r * 8;
#pragma unroll
                for (int q = 0; q < 8; q++) {
                    ulonglong2 z = row[q];          // uniform address -> broadcast
                    fma2(acc[2 * q],     z.x, dup);
                    fma2(acc[2 * q + 1], z.y, dup);
                }
            }
        }

        if (!LAST) {
            if (act) {
                float4* o4 = reinterpret_cast<float4*>(g_vbuf + e * RANK);
#pragma unroll
                for (int q = 0; q < 8; q++) {
                    float a, b, c, d;
                    unpack2(acc[2 * q],     a, b);
                    unpack2(acc[2 * q + 1], c, d);
                    o4[q] = make_float4(a, b, c, d);
                }
            }
        } else {
            if (act) {
                int zrow = get_idx(raw, e, 6, is64) * NDIM + get_idx(raw, e, 7, is64);
                const ulonglong2* zp =
                    reinterpret_cast<const ulonglong2*>(g_Z + zrow * RANK);
                ull d = 0ull;
#pragma unroll
                for (int q = 0; q < 8; q++) {
                    ulonglong2 z = zp[q];
                    fma2(d, acc[2 * q],     z.x);
                    fma2(d, acc[2 * q + 1], z.y);
                }
                float a, c;
                unpack2(d, a, c);
                out[e] = a + c;
            }
        }
    }
}

extern "C" void kernel_launch(void* const* d_in, const int* in_sizes, int n_in,
                              void* d_out, int out_size) {
    const int32_t* indices  = (const int32_t*)d_in[0];
    const float*   core0    = (const float*)d_in[1];
    const float*   coresmid = (const float*)d_in[2];
    const float*   corelast = (const float*)d_in[3];
    float*         out      = (float*)d_out;

    k1_prep<<<1216, 256>>>(indices, core0, coresmid, corelast);
    k2_scan<<<2, 1024>>>();
    k3_scatter<<<256, 256>>>(indices);

    float* p1;  cudaGetSymbolAddress((void**)&p1, g_P1);
    float* p2;  cudaGetSymbolAddress((void**)&p2, g_P2);
    step_kernel<true,  false><<<NPAIR / 8, 256>>>(0, indices, p1, out);
    step_kernel<false, true ><<<NPAIR / 8, 256>>>(1, indices, p2, out);
}

// round 7
// speedup vs baseline: 1.1693x; 1.1693x over previous
#include <cuda_runtime.h>
#include <cstdint>

#define B_TOTAL 131072
#define NDIM 64
#define RANK 32
#define NPAIR (NDIM * NDIM)
#define MID_STRIDE (RANK*NDIM*RANK)
#define ROW_STRIDE (NDIM*RANK)

typedef unsigned long long ull;

__device__ float g_vbuf[B_TOTAL * RANK];
__device__ float g_A[NPAIR * RANK];
__device__ float g_Z[NPAIR * RANK];
__device__ float g_P1[NPAIR * RANK * RANK];
__device__ float g_P2[NPAIR * RANK * RANK];
__device__ int   g_perm[2][B_TOTAL];
__device__ int   g_hist[2][NPAIR];
__device__ int   g_base[2][NPAIR + 1];
__device__ int   g_cur[2][NPAIR];

__device__ __forceinline__ int sniff64(const int32_t* raw) {
    unsigned int h = 0;
#pragma unroll
    for (int i = 0; i < 16; i++) h |= (unsigned int)raw[2 * i + 1];
    return (h == 0u) ? 1 : 0;
}
__device__ __forceinline__ int get_idx(const int32_t* raw, int e, int k, int is64) {
    int t;
    if (is64) t = (int)((const long long*)raw)[(long long)e * 8 + k];
    else      t = raw[e * 8 + k];
    return min(max(t, 0), NDIM - 1);
}
__device__ __forceinline__ ull pack2(float x, float y) {
    ull r; asm("mov.b64 %0,{%1,%2};" : "=l"(r) : "f"(x), "f"(y)); return r;
}
__device__ __forceinline__ void unpack2(ull v, float& x, float& y) {
    asm("mov.b64 {%0,%1},%2;" : "=f"(x), "=f"(y) : "l"(v));
}
__device__ __forceinline__ void fma2(ull& d, ull a, ull b) {
    asm("fma.rn.f32x2 %0,%1,%2,%0;" : "+l"(d) : "l"(a), "l"(b));
}

// ============================================================================
// K1: histogram + A + Z + P1 + P2 (one launch, independent block roles)
// ============================================================================
__global__ __launch_bounds__(256)
void k1_prep(const int32_t* __restrict__ raw,
             const float* __restrict__ core0,
             const float* __restrict__ mids,
             const float* __restrict__ cl) {
    __shared__ float S[RANK * 34];
    const int b = blockIdx.x, tid = threadIdx.x;
    const int warp = tid >> 5, lane = tid & 31;

    if (b < 64) {
        const int is64 = sniff64(raw);
#pragma unroll
        for (int i = 0; i < 8; i++) {
            const int e = b * 2048 + i * 256 + tid;
            int k0 = get_idx(raw, e, 2, is64) * NDIM + get_idx(raw, e, 3, is64);
            int k1 = get_idx(raw, e, 4, is64) * NDIM + get_idx(raw, e, 5, is64);
            atomicAdd(&g_hist[0][k0], 1);
            atomicAdd(&g_hist[1][k1], 1);
        }
    } else if (b < 128) {
        const int j0 = b - 64;
        if (tid < RANK) S[tid] = core0[j0 * RANK + tid];
        __syncthreads();
#pragma unroll
        for (int t = 0; t < 8; t++) {
            const int j1 = warp * 8 + t;
            float acc = 0.0f;
#pragma unroll
            for (int r = 0; r < RANK; r++)
                acc = fmaf(S[r], mids[r * ROW_STRIDE + j1 * RANK + lane], acc);
            g_A[(j0 * NDIM + j1) * RANK + lane] = acc;
        }
    } else if (b < 192) {
        const int j6 = b - 128;
        const float* M5 = mids + 5 * MID_STRIDE;
        for (int i = tid; i < RANK * RANK; i += 256) {
            int r = i >> 5, s = i & 31;
            S[s * 34 + r] = M5[r * ROW_STRIDE + j6 * RANK + s];
        }
        __syncthreads();
#pragma unroll
        for (int t = 0; t < 8; t++) {
            const int j7 = warp * 8 + t;
            float acc = 0.0f;
#pragma unroll
            for (int s = 0; s < RANK; s++)
                acc = fmaf(cl[s * NDIM + j7], S[s * 34 + lane], acc);
            g_Z[(j6 * NDIM + j7) * RANK + lane] = acc;
        }
    } else {
        // pair folds: P[ja,jb][r][s] = sum_m Ma[r,ja,m] * Mb[m,jb,s]
        const int which = (b < 704) ? 0 : 1;
        const int x = b - (which ? 704 : 192);
        const int ja = x >> 3;
        const float* Ma = mids + (which ? 3 : 1) * MID_STRIDE;
        const float* Mb = mids + (which ? 4 : 2) * MID_STRIDE;
        float* P = which ? g_P2 : g_P1;

        for (int i = tid; i < RANK * RANK; i += 256) {
            int r = i >> 5, m = i & 31;
            S[m * 34 + r] = Ma[r * ROW_STRIDE + ja * RANK + m];
        }
        __syncthreads();

        const int jb = (x & 7) * 8 + warp;
        float m2[RANK];
#pragma unroll
        for (int m = 0; m < RANK; m++)
            m2[m] = Mb[m * ROW_STRIDE + jb * RANK + lane];

        ull acc2[16];
#pragma unroll
        for (int q = 0; q < 16; q++) acc2[q] = 0ull;
#pragma unroll
        for (int m = 0; m < RANK; m++) {
            const ull dup = pack2(m2[m], m2[m]);
            const ull* Sp = reinterpret_cast<const ull*>(S + m * 34);
#pragma unroll
            for (int rp = 0; rp < 16; rp++) fma2(acc2[rp], Sp[rp], dup);
        }
        float* Pp = P + (ja * NDIM + jb) * (RANK * RANK);
#pragma unroll
        for (int rp = 0; rp < 16; rp++) {
            float a, c;
            unpack2(acc2[rp], a, c);
            Pp[(2 * rp) * RANK + lane]     = a;
            Pp[(2 * rp + 1) * RANK + lane] = c;
        }
    }
}

// ============================================================================
// K2: exclusive scan; init cursors; reset hist for next graph replay
// ============================================================================
__global__ __launch_bounds__(1024)
void k2_scan() {
    __shared__ int sh[1024];
    const int m = blockIdx.x, t = threadIdx.x;
    int4 v4 = reinterpret_cast<const int4*>(g_hist[m])[t];
    int vals[4] = {v4.x, v4.y, v4.z, v4.w};
    int s = vals[0] + vals[1] + vals[2] + vals[3];
    sh[t] = s;
    __syncthreads();
    for (int off = 1; off < 1024; off <<= 1) {
        int u = (t >= off) ? sh[t - off] : 0;
        __syncthreads();
        sh[t] += u;
        __syncthreads();
    }
    int run = sh[t] - s;
#pragma unroll
    for (int i = 0; i < 4; i++) {
        int bin = t * 4 + i;
        g_base[m][bin] = run;
        g_cur[m][bin]  = run;
        g_hist[m][bin] = 0;
        run += vals[i];
    }
    if (t == 1023) g_base[m][NPAIR] = B_TOTAL;
}

// ============================================================================
// K3: scatter via spread global atomics
// ============================================================================
__global__ __launch_bounds__(256)
void k3_scatter(const int32_t* __restrict__ raw) {
    const int is64 = sniff64(raw);
    for (int e = blockIdx.x * 256 + threadIdx.x; e < B_TOTAL; e += gridDim.x * 256) {
        int k0 = get_idx(raw, e, 2, is64) * NDIM + get_idx(raw, e, 3, is64);
        int k1 = get_idx(raw, e, 4, is64) * NDIM + get_idx(raw, e, 5, is64);
        g_perm[0][atomicAdd(&g_cur[0][k0], 1)] = e;
        g_perm[1][atomicAdd(&g_cur[1][k1], 1)] = e;
    }
}

// ============================================================================
// K4/K5: bucketed matvec. 8 warps/block, warp-per-bin, slice in SMEM,
// lane-owns-element (direct 128B v row load/store, no staging transpose).
// launch_bounds(256,2) -> 128-reg budget: NO spills (R6 lesson).
// acc[i] covers output floats {2i, 2i+1}.
// ============================================================================
template <bool FIRST, bool LAST>
__global__ __launch_bounds__(256, 2)
void step_kernel(int S, const int32_t* __restrict__ raw,
                 const float* __restrict__ Ptab, float* __restrict__ out) {
    __shared__ __align__(16) float slice[8][RANK * RANK];
    const int warp = threadIdx.x >> 5, lane = threadIdx.x & 31;
    const int bin = blockIdx.x * 8 + warp;
    const int lo = g_base[S][bin], hi = g_base[S][bin + 1];
    if (lo >= hi) return;

    // cooperative per-warp slice load: 8 coalesced LDG.128 per lane
    {
        float4* s4 = reinterpret_cast<float4*>(slice[warp]);
        const float4* p4 = reinterpret_cast<const float4*>(Ptab + bin * (RANK * RANK));
#pragma unroll
        for (int i = 0; i < 8; i++) s4[i * 32 + lane] = p4[i * 32 + lane];
    }
    __syncwarp();

    const int is64 = sniff64(raw);
    const float* sl = slice[warp];

    for (int base = lo; base < hi; base += 32) {
        const bool act = (base + lane < hi);
        const int e = g_perm[S][act ? base + lane : base];

        const float4* __restrict__ v4;
        if (FIRST) {
            int rowidx = get_idx(raw, e, 0, is64) * NDIM + get_idx(raw, e, 1, is64);
            v4 = reinterpret_cast<const float4*>(g_A + rowidx * RANK);
        } else {
            v4 = reinterpret_cast<const float4*>(g_vbuf + e * RANK);
        }

        ull acc[16];
#pragma unroll
        for (int q = 0; q < 16; q++) acc[q] = 0ull;

#pragma unroll
        for (int g = 0; g < 8; g++) {
            const float4 v = v4[g];                      // one LDG.128 per g
            const float vs[4] = {v.x, v.y, v.z, v.w};
#pragma unroll
            for (int t = 0; t < 4; t++) {
                const int r = g * 4 + t;
                const ull dup = pack2(vs[t], vs[t]);
                const ulonglong2* __restrict__ row =
                    reinterpret_cast<const ulonglong2*>(sl + r * RANK);
#pragma unroll
                for (int q = 0; q < 8; q++) {
                    ulonglong2 z = row[q];               // broadcast LDS.128
                    fma2(acc[2 * q],     z.x, dup);
                    fma2(acc[2 * q + 1], z.y, dup);
                }
            }
        }

        if (!LAST) {
            if (act) {
                float4* o4 = reinterpret_cast<float4*>(g_vbuf + e * RANK);
#pragma unroll
                for (int q = 0; q < 8; q++) {
                    float a, b2, c, d2;
                    unpack2(acc[2 * q],     a, b2);
                    unpack2(acc[2 * q + 1], c, d2);
                    o4[q] = make_float4(a, b2, c, d2);
                }
            }
        } else {
            if (act) {
                int zrow = get_idx(raw, e, 6, is64) * NDIM + get_idx(raw, e, 7, is64);
                const ulonglong2* zp =
                    reinterpret_cast<const ulonglong2*>(g_Z + zrow * RANK);
                ull d = 0ull;
#pragma unroll
                for (int q = 0; q < 8; q++) {
                    ulonglong2 z = zp[q];
                    fma2(d, acc[2 * q],     z.x);
                    fma2(d, acc[2 * q + 1], z.y);
                }
                float a, c;
                unpack2(d, a, c);
                out[e] = a + c;
            }
        }
    }
}

extern "C" void kernel_launch(void* const* d_in, const int* in_sizes, int n_in,
                              void* d_out, int out_size) {
    const int32_t* indices  = (const int32_t*)d_in[0];
    const float*   core0    = (const float*)d_in[1];
    const float*   coresmid = (const float*)d_in[2];
    const float*   corelast = (const float*)d_in[3];
    float*         out      = (float*)d_out;

    k1_prep<<<1216, 256>>>(indices, core0, coresmid, corelast);
    k2_scan<<<2, 1024>>>();
    k3_scatter<<<256, 256>>>(indices);

    float* p1;  cudaGetSymbolAddress((void**)&p1, g_P1);
    float* p2;  cudaGetSymbolAddress((void**)&p2, g_P2);
    step_kernel<true,  false><<<NPAIR / 8, 256>>>(0, indices, p1, out);
    step_kernel<false, true ><<<NPAIR / 8, 256>>>(1, indices, p2, out);
}

// round 8
// speedup vs baseline: 5.7522x; 4.9192x over previous
#include <cuda_runtime.h>
#include <cstdint>

#define B_TOTAL 131072
#define NDIM 64
#define RANK 32
#define NPAIR (NDIM * NDIM)
#define MID_STRIDE (RANK*NDIM*RANK)
#define ROW_STRIDE (NDIM*RANK)

typedef unsigned long long ull;

__device__ float g_vbuf[B_TOTAL * RANK];
__device__ float g_A[NPAIR * RANK];
__device__ float g_Z[NPAIR * RANK];
__device__ float g_P1[NPAIR * RANK * RANK];
__device__ float g_P2[NPAIR * RANK * RANK];
__device__ int   g_perm[2][B_TOTAL];
__device__ int   g_hist[2][NPAIR];
__device__ int   g_base[2][NPAIR + 1];
__device__ int   g_cur[2][NPAIR];

__device__ __forceinline__ int sniff64(const int32_t* raw) {
    unsigned int h = 0;
#pragma unroll
    for (int i = 0; i < 16; i++) h |= (unsigned int)raw[2 * i + 1];
    return (h == 0u) ? 1 : 0;
}
__device__ __forceinline__ int get_idx(const int32_t* raw, int e, int k, int is64) {
    int t;
    if (is64) t = (int)((const long long*)raw)[(long long)e * 8 + k];
    else      t = raw[e * 8 + k];
    return min(max(t, 0), NDIM - 1);
}
__device__ __forceinline__ ull pack2(float x, float y) {
    ull r; asm("mov.b64 %0,{%1,%2};" : "=l"(r) : "f"(x), "f"(y)); return r;
}
__device__ __forceinline__ void unpack2(ull v, float& x, float& y) {
    asm("mov.b64 {%0,%1},%2;" : "=f"(x), "=f"(y) : "l"(v));
}
__device__ __forceinline__ void fma2(ull& d, ull a, ull b) {
    asm("fma.rn.f32x2 %0,%1,%2,%0;" : "+l"(d) : "l"(a), "l"(b));
}

// ============================================================================
// K1: histogram + A + Z + P1 + P2 (one launch, independent block roles)
// ============================================================================
__global__ __launch_bounds__(256)
void k1_prep(const int32_t* __restrict__ raw,
             const float* __restrict__ core0,
             const float* __restrict__ mids,
             const float* __restrict__ cl) {
    __shared__ float S[RANK * 34];
    const int b = blockIdx.x, tid = threadIdx.x;
    const int warp = tid >> 5, lane = tid & 31;

    if (b < 64) {
        const int is64 = sniff64(raw);
#pragma unroll
        for (int i = 0; i < 8; i++) {
            const int e = b * 2048 + i * 256 + tid;
            int k0 = get_idx(raw, e, 2, is64) * NDIM + get_idx(raw, e, 3, is64);
            int k1 = get_idx(raw, e, 4, is64) * NDIM + get_idx(raw, e, 5, is64);
            atomicAdd(&g_hist[0][k0], 1);
            atomicAdd(&g_hist[1][k1], 1);
        }
    } else if (b < 128) {
        const int j0 = b - 64;
        if (tid < RANK) S[tid] = core0[j0 * RANK + tid];
        __syncthreads();
#pragma unroll
        for (int t = 0; t < 8; t++) {
            const int j1 = warp * 8 + t;
            float acc = 0.0f;
#pragma unroll
            for (int r = 0; r < RANK; r++)
                acc = fmaf(S[r], mids[r * ROW_STRIDE + j1 * RANK + lane], acc);
            g_A[(j0 * NDIM + j1) * RANK + lane] = acc;
        }
    } else if (b < 192) {
        const int j6 = b - 128;
        const float* M5 = mids + 5 * MID_STRIDE;
        for (int i = tid; i < RANK * RANK; i += 256) {
            int r = i >> 5, s = i & 31;
            S[s * 34 + r] = M5[r * ROW_STRIDE + j6 * RANK + s];
        }
        __syncthreads();
#pragma unroll
        for (int t = 0; t < 8; t++) {
            const int j7 = warp * 8 + t;
            float acc = 0.0f;
#pragma unroll
            for (int s = 0; s < RANK; s++)
                acc = fmaf(cl[s * NDIM + j7], S[s * 34 + lane], acc);
            g_Z[(j6 * NDIM + j7) * RANK + lane] = acc;
        }
    } else {
        // pair folds: P[ja,jb][r][s] = sum_m Ma[r,ja,m] * Mb[m,jb,s]
        const int which = (b < 704) ? 0 : 1;
        const int x = b - (which ? 704 : 192);
        const int ja = x >> 3;
        const float* Ma = mids + (which ? 3 : 1) * MID_STRIDE;
        const float* Mb = mids + (which ? 4 : 2) * MID_STRIDE;
        float* P = which ? g_P2 : g_P1;

        for (int i = tid; i < RANK * RANK; i += 256) {
            int r = i >> 5, m = i & 31;
            S[m * 34 + r] = Ma[r * ROW_STRIDE + ja * RANK + m];
        }
        __syncthreads();

        const int jb = (x & 7) * 8 + warp;
        float m2[RANK];
#pragma unroll
        for (int m = 0; m < RANK; m++)
            m2[m] = Mb[m * ROW_STRIDE + jb * RANK + lane];

        ull acc2[16];
#pragma unroll
        for (int q = 0; q < 16; q++) acc2[q] = 0ull;
#pragma unroll
        for (int m = 0; m < RANK; m++) {
            const ull dup = pack2(m2[m], m2[m]);
            const ull* Sp = reinterpret_cast<const ull*>(S + m * 34);
#pragma unroll
            for (int rp = 0; rp < 16; rp++) fma2(acc2[rp], Sp[rp], dup);
        }
        float* Pp = P + (ja * NDIM + jb) * (RANK * RANK);
#pragma unroll
        for (int rp = 0; rp < 16; rp++) {
            float a, c;
            unpack2(acc2[rp], a, c);
            Pp[(2 * rp) * RANK + lane]     = a;
            Pp[(2 * rp + 1) * RANK + lane] = c;
        }
    }
}

// ============================================================================
// K2: exclusive scan; init cursors; reset hist for next graph replay
// ============================================================================
__global__ __launch_bounds__(1024)
void k2_scan() {
    __shared__ int sh[1024];
    const int m = blockIdx.x, t = threadIdx.x;
    int4 v4 = reinterpret_cast<const int4*>(g_hist[m])[t];
    int vals[4] = {v4.x, v4.y, v4.z, v4.w};
    int s = vals[0] + vals[1] + vals[2] + vals[3];
    sh[t] = s;
    __syncthreads();
    for (int off = 1; off < 1024; off <<= 1) {
        int u = (t >= off) ? sh[t - off] : 0;
        __syncthreads();
        sh[t] += u;
        __syncthreads();
    }
    int run = sh[t] - s;
#pragma unroll
    for (int i = 0; i < 4; i++) {
        int bin = t * 4 + i;
        g_base[m][bin] = run;
        g_cur[m][bin]  = run;
        g_hist[m][bin] = 0;
        run += vals[i];
    }
    if (t == 1023) g_base[m][NPAIR] = B_TOTAL;
}

// ============================================================================
// K3: scatter via spread global atomics
// ============================================================================
__global__ __launch_bounds__(256)
void k3_scatter(const int32_t* __restrict__ raw) {
    const int is64 = sniff64(raw);
    for (int e = blockIdx.x * 256 + threadIdx.x; e < B_TOTAL; e += gridDim.x * 256) {
        int k0 = get_idx(raw, e, 2, is64) * NDIM + get_idx(raw, e, 3, is64);
        int k1 = get_idx(raw, e, 4, is64) * NDIM + get_idx(raw, e, 5, is64);
        g_perm[0][atomicAdd(&g_cur[0][k0], 1)] = e;
        g_perm[1][atomicAdd(&g_cur[1][k1], 1)] = e;
    }
}

// ============================================================================
// K4/K5: bucketed matvec — R5's proven inner loop (regs 84, no spills),
// repackaged as 4 warps per 128-thread block (warp = bin) for occupancy.
// NO register cap (launch_bounds caps caused the R6/R7 spill cascades).
// ============================================================================
template <bool FIRST, bool LAST>
__global__ __launch_bounds__(128)
void step_kernel(int S, const int32_t* __restrict__ raw,
                 const float* __restrict__ Ptab, float* __restrict__ out) {
    __shared__ __align__(16) float slice_s[4][RANK * RANK];  // 16 KB
    __shared__ float stage_s[4][RANK * 33];                  // 16.9 KB
    const int warp = threadIdx.x >> 5, lane = threadIdx.x & 31;
    const int bin = blockIdx.x * 4 + warp;
    const int lo = g_base[S][bin], hi = g_base[S][bin + 1];
    if (lo >= hi) return;

    float* slice = slice_s[warp];
    float* st    = stage_s[warp];

    // per-warp contiguous 4 KB slice load (8 coalesced LDG.128 per lane)
    {
        const float4* src4 = reinterpret_cast<const float4*>(Ptab + bin * (RANK * RANK));
        float4* dst4 = reinterpret_cast<float4*>(slice);
#pragma unroll
        for (int i = 0; i < 8; i++) dst4[i * 32 + lane] = src4[i * 32 + lane];
    }
    const int is64 = (FIRST || LAST) ? sniff64(raw) : 0;
    __syncwarp();

    for (int base = lo; base < hi; base += 32) {
        const int n = min(32, hi - base);
        int e = 0, rowidx = 0;
        if (lane < n) {
            e = g_perm[S][base + lane];
            rowidx = FIRST ? (get_idx(raw, e, 0, is64) * NDIM + get_idx(raw, e, 1, is64))
                           : e;
        }
        const float* src = FIRST ? g_A : g_vbuf;
        __syncwarp();
        for (int w = 0; w < n; w++) {
            int re = __shfl_sync(0xffffffffu, rowidx, w);
            st[w * 33 + lane] = src[re * RANK + lane];
        }
        __syncwarp();

        ull acc[16];
#pragma unroll
        for (int q = 0; q < 16; q++) acc[q] = 0ull;
#pragma unroll 8
        for (int r = 0; r < RANK; r++) {
            float vr = st[lane * 33 + r];
            ull v2 = pack2(vr, vr);
            const ulonglong2* sp = reinterpret_cast<const ulonglong2*>(slice + r * RANK);
#pragma unroll
            for (int q = 0; q < 8; q++) {
                ulonglong2 z = sp[q];
                fma2(acc[2 * q],     z.x, v2);
                fma2(acc[2 * q + 1], z.y, v2);
            }
        }

        if (!LAST) {
            __syncwarp();
#pragma unroll
            for (int q = 0; q < 16; q++) {
                float a, c;
                unpack2(acc[q], a, c);
                st[lane * 33 + 2 * q]     = a;
                st[lane * 33 + 2 * q + 1] = c;
            }
            __syncwarp();
            for (int w = 0; w < n; w++) {
                int ee = __shfl_sync(0xffffffffu, e, w);
                g_vbuf[ee * RANK + lane] = st[w * 33 + lane];
            }
        } else {
            if (lane < n) {
                int zrow = get_idx(raw, e, 6, is64) * NDIM + get_idx(raw, e, 7, is64);
                const ull* zp = reinterpret_cast<const ull*>(g_Z + zrow * RANK);
                ull d = 0ull;
#pragma unroll
                for (int q = 0; q < 16; q++) fma2(d, acc[q], zp[q]);
                float a, c;
                unpack2(d, a, c);
                out[e] = a + c;
            }
        }
    }
}

extern "C" void kernel_launch(void* const* d_in, const int* in_sizes, int n_in,
                              void* d_out, int out_size) {
    const int32_t* indices  = (const int32_t*)d_in[0];
    const float*   core0    = (const float*)d_in[1];
    const float*   coresmid = (const float*)d_in[2];
    const float*   corelast = (const float*)d_in[3];
    float*         out      = (float*)d_out;

    k1_prep<<<1216, 256>>>(indices, core0, coresmid, corelast);
    k2_scan<<<2, 1024>>>();
    k3_scatter<<<256, 256>>>(indices);

    float* p1;  cudaGetSymbolAddress((void**)&p1, g_P1);
    float* p2;  cudaGetSymbolAddress((void**)&p2, g_P2);
    step_kernel<true,  false><<<NPAIR / 4, 128>>>(0, indices, p1, out);
    step_kernel<false, true ><<<NPAIR / 4, 128>>>(1, indices, p2, out);
}